// round 7
// baseline (speedup 1.0000x reference)
#include <cuda_runtime.h>
#include <cstdint>

#define C_TOT 256
#define H_TOT 56
#define W_TOT 56
#define HW    3136
#define M_TOT 100352   // 32*56*56
#define CI    1024

// ---------------- scratch (static device globals; no allocations) ----------
__device__ float g_y[(size_t)M_TOT * C_TOT];   // NHWC, BN'd, tf32-rounded
__device__ float g_h[(size_t)M_TOT * CI];      // GELU output, tf32-rounded
__device__ float g_w1[CI * C_TOT];             // fc1_w tf32-rounded
__device__ float g_w2[C_TOT * CI];             // fc2_w tf32-rounded

__device__ __forceinline__ float to_tf32(float x) {
    uint32_t u;
    asm("cvt.rna.tf32.f32 %0, %1;" : "=r"(u) : "f"(x));
    return __uint_as_float(u);
}
__device__ __forceinline__ float gelu_exact(float v) {
    return 0.5f * v * (1.0f + erff(v * 0.70710678118654752440f));
}

// ---------------- kernel 1: round weights to tf32 --------------------------
__global__ void convert_weights_kernel(const float* __restrict__ fc1,
                                       const float* __restrict__ fc2) {
    int i = blockIdx.x * blockDim.x + threadIdx.x;
    if (i < CI * C_TOT) {
        g_w1[i] = to_tf32(fc1[i]);
        g_w2[i] = to_tf32(fc2[i]);
    }
}

// ---------------- kernel 2: NeoCell + BN -> y (NHWC, tf32) ------------------
__global__ __launch_bounds__(256)
void neocell_bn_kernel(const float* __restrict__ x,
                       const float* __restrict__ wa1, const float* __restrict__ wb1,
                       const float* __restrict__ wa2, const float* __restrict__ wb2,
                       const float* __restrict__ bnw, const float* __restrict__ bnb,
                       const float* __restrict__ bnm, const float* __restrict__ bnv) {
    __shared__ float tile[32 * 229];
    const int hs = blockIdx.x;
    const int c0 = blockIdx.y * 32;
    const int b  = blockIdx.z;
    const int h0 = hs * 4;

    const float* xb = x + ((size_t)b * C_TOT + c0) * HW + (size_t)h0 * W_TOT;
    for (int idx = threadIdx.x; idx < 32 * 4 * 56; idx += 256) {
        int c = idx / 224, r = idx % 224;
        int hh = r / 56, w = r % 56;
        tile[c * 229 + hh * 57 + w] = xb[(size_t)c * HW + hh * W_TOT + w];
    }
    __syncthreads();

    const int t  = threadIdx.x;
    const int c  = t & 31;
    const int s  = t >> 5;
    const int gc = c0 + c;
    const float scale = bnw[gc] * rsqrtf(bnv[gc] + 1e-5f);
    const float shift = bnb[gc] - bnm[gc] * scale;
    float* ybase = g_y + ((size_t)b * H_TOT + h0) * W_TOT * C_TOT + gc;
    const float* tc = tile + c * 229;

    if (gc < 128) {
        const float a00 = wa1[gc*4+0], a01 = wa1[gc*4+1], a10 = wa1[gc*4+2], a11 = wa1[gc*4+3];
        const float b00 = wb1[gc*4+0], b01 = wb1[gc*4+1], b10 = wb1[gc*4+2], b11 = wb1[gc*4+3];
        for (int bi = s; bi < 56; bi += 8) {
            int n = bi / 28, m = bi % 28;
            const float* tp = tc + n * 2 * 57 + m * 2;
            float x00 = tp[0],  x01 = tp[1];
            float x10 = tp[57], x11 = tp[58];
            float t00 = a00 * x00 + a01 * x10;
            float t01 = a00 * x01 + a01 * x11;
            float t10 = a10 * x00 + a11 * x10;
            float t11 = a10 * x01 + a11 * x11;
            float y00 = t00 * b00 + t01 * b10;
            float y01 = t00 * b01 + t01 * b11;
            float y10 = t10 * b00 + t11 * b10;
            float y11 = t10 * b01 + t11 * b11;
            size_t base = ((size_t)(n * 2) * 56 + m * 2) * (size_t)C_TOT;
            ybase[base]            = to_tf32(y00 * scale + shift);
            ybase[base + 256]      = to_tf32(y01 * scale + shift);
            ybase[base + 56 * 256] = to_tf32(y10 * scale + shift);
            ybase[base + 57 * 256] = to_tf32(y11 * scale + shift);
        }
    } else {
        const float* wap = wa2 + (size_t)(gc - 128) * 16;
        const float* wbp = wb2 + (size_t)(gc - 128) * 16;
        float a[4][4], bw[4][4];
        #pragma unroll
        for (int i = 0; i < 4; i++)
            #pragma unroll
            for (int j = 0; j < 4; j++) { a[i][j] = wap[i*4+j]; bw[i][j] = wbp[i*4+j]; }
        for (int m = s; m < 14; m += 8) {
            float xv[4][4];
            #pragma unroll
            for (int i = 0; i < 4; i++)
                #pragma unroll
                for (int j = 0; j < 4; j++) xv[i][j] = tc[i * 57 + m * 4 + j];
            float tv[4][4];
            #pragma unroll
            for (int p = 0; p < 4; p++)
                #pragma unroll
                for (int j = 0; j < 4; j++)
                    tv[p][j] = a[p][0]*xv[0][j] + a[p][1]*xv[1][j]
                             + a[p][2]*xv[2][j] + a[p][3]*xv[3][j];
            #pragma unroll
            for (int p = 0; p < 4; p++)
                #pragma unroll
                for (int q = 0; q < 4; q++) {
                    float v = tv[p][0]*bw[0][q] + tv[p][1]*bw[1][q]
                            + tv[p][2]*bw[2][q] + tv[p][3]*bw[3][q];
                    ybase[((size_t)(p * 56) + m * 4 + q) * (size_t)C_TOT] =
                        to_tf32(v * scale + shift);
                }
        }
    }
}

// ---------------- GEMM (TN: C[m,n] = sum_k A[m,k]*B[n,k]), tf32 mma --------
// CTA tile 128x128, BK=16, 4 warps (2m x 2n), warp tile 64x64 (CUTLASS-style).
// 4-stage cp.async ring, single __syncthreads per K-iteration, pipelined B frags.
#define BKQ        16
#define LDSTRIDE   20                   // 16 + 4 pad -> conflict-free LDSM
#define STAGE_F    (128 * LDSTRIDE)     // floats per matrix per stage
#define NSTAGE     4
#define GSMEM      (NSTAGE * 2 * STAGE_F * 4)   // 81920 bytes

template<int K, int MODE>
__global__ __launch_bounds__(128, 2)
void gemm_tn_kernel(float* __restrict__ outp, const float* __restrict__ xres) {
    extern __shared__ __align__(16) float sm[];
    const float* Amat = (MODE == 1) ? g_y : g_h;
    const float* Bmat = (MODE == 1) ? g_w1 : g_w2;
    constexpr int KT = K / BKQ;

    const int tid  = threadIdx.x;
    const int lane = tid & 31;
    const int warp = tid >> 5;
    const int wm   = warp & 1;          // 2 m-warps
    const int wn   = warp >> 1;         // 2 n-warps
    const int bm   = blockIdx.y * 128;
    const int bn   = blockIdx.x * 128;

    // global -> smem staging: 4 threads per row (16 floats), 32 rows/pass, 4 passes
    const int lrow = tid >> 2;          // 0..31
    const int lk   = (tid & 3) * 4;
    const float* Ap = Amat + (size_t)(bm + lrow) * K + lk;
    const float* Bp = Bmat + (size_t)(bn + lrow) * K + lk;

    const uint32_t smb = (uint32_t)__cvta_generic_to_shared(sm);
    // per-stage layout: [A(128x20) | B(128x20)]
    const uint32_t sa  = smb + (uint32_t)(lrow * LDSTRIDE + lk) * 4u;
    const uint32_t sb  = sa + (uint32_t)STAGE_F * 4u;

    float acc[4][8][4];
    #pragma unroll
    for (int i = 0; i < 4; i++)
        #pragma unroll
        for (int j = 0; j < 8; j++)
            #pragma unroll
            for (int q = 0; q < 4; q++) acc[i][j][q] = 0.f;

    // ldmatrix source addressing (fragment layouts per PTX m16n8k8 tf32)
    const int arow = lane & 15;
    const int ak   = (lane >> 4) * 4;
    const int brow = (lane & 7) + ((lane >> 4) << 3);
    const int bk   = ((lane >> 3) & 1) * 4;
    const uint32_t abase = smb + (uint32_t)((wm * 64 + arow) * LDSTRIDE + ak) * 4u;
    const uint32_t bbase = smb + (uint32_t)(STAGE_F + (wn * 64 + brow) * LDSTRIDE + bk) * 4u;

#define PREFETCH(ktv, stv) do {                                                          \
    const float* ap_ = Ap + (ktv) * BKQ;                                                 \
    const float* bp_ = Bp + (ktv) * BKQ;                                                 \
    uint32_t so_ = (uint32_t)((stv) * 2 * STAGE_F * 4);                                  \
    _Pragma("unroll")                                                                    \
    for (int rp_ = 0; rp_ < 4; rp_++) {                                                  \
        asm volatile("cp.async.cg.shared.global [%0], [%1], 16;\n"                       \
                     :: "r"(sa + so_ + (uint32_t)(rp_ * 32 * LDSTRIDE * 4)),             \
                        "l"(ap_ + (size_t)(rp_ * 32) * K));                              \
        asm volatile("cp.async.cg.shared.global [%0], [%1], 16;\n"                       \
                     :: "r"(sb + so_ + (uint32_t)(rp_ * 32 * LDSTRIDE * 4)),             \
                        "l"(bp_ + (size_t)(rp_ * 32) * K));                              \
    }                                                                                    \
    asm volatile("cp.async.commit_group;\n");                                            \
} while (0)

#define LDSM(dst, addr)                                                                  \
    asm volatile("ldmatrix.sync.aligned.m8n8.x4.shared.b16 {%0,%1,%2,%3}, [%4];\n"       \
        : "=r"((dst)[0]), "=r"((dst)[1]), "=r"((dst)[2]), "=r"((dst)[3]) : "r"(addr))

#define MMA_PAIR(accj, afr, b0, b1)                                                      \
    asm volatile("mma.sync.aligned.m16n8k8.row.col.f32.tf32.tf32.f32 "                   \
        "{%0,%1,%2,%3}, {%4,%5,%6,%7}, {%8,%9}, {%0,%1,%2,%3};\n"                        \
        : "+f"((accj)[0]), "+f"((accj)[1]), "+f"((accj)[2]), "+f"((accj)[3])             \
        : "r"((afr)[0]), "r"((afr)[1]), "r"((afr)[2]), "r"((afr)[3]),                    \
          "r"(b0), "r"(b1))

#define MMA_J(jj, bfr) do {                                                              \
    MMA_PAIR(acc[0][2*(jj)],   af[0], (bfr)[0], (bfr)[1]);                               \
    MMA_PAIR(acc[0][2*(jj)+1], af[0], (bfr)[2], (bfr)[3]);                               \
    MMA_PAIR(acc[1][2*(jj)],   af[1], (bfr)[0], (bfr)[1]);                               \
    MMA_PAIR(acc[1][2*(jj)+1], af[1], (bfr)[2], (bfr)[3]);                               \
    MMA_PAIR(acc[2][2*(jj)],   af[2], (bfr)[0], (bfr)[1]);                               \
    MMA_PAIR(acc[2][2*(jj)+1], af[2], (bfr)[2], (bfr)[3]);                               \
    MMA_PAIR(acc[3][2*(jj)],   af[3], (bfr)[0], (bfr)[1]);                               \
    MMA_PAIR(acc[3][2*(jj)+1], af[3], (bfr)[2], (bfr)[3]);                               \
} while (0)

    // prologue: fill stages 0..2
    PREFETCH(0, 0);
    PREFETCH(1, 1);
    PREFETCH(2, 2);

    for (int kt = 0; kt < KT; ++kt) {
        const int st = kt & (NSTAGE - 1);
        if (kt + 2 < KT)      asm volatile("cp.async.wait_group 2;\n");
        else if (kt + 1 < KT) asm volatile("cp.async.wait_group 1;\n");
        else                  asm volatile("cp.async.wait_group 0;\n");
        __syncthreads();
        if (kt + 3 < KT) PREFETCH(kt + 3, (kt + 3) & (NSTAGE - 1));

        const uint32_t soff = (uint32_t)(st * 2 * STAGE_F * 4);
        #pragma unroll
        for (int s = 0; s < 2; s++) {
            uint32_t af[4][4];
            #pragma unroll
            for (int mt = 0; mt < 4; mt++)
                LDSM(af[mt], abase + soff + (uint32_t)((mt * 16 * LDSTRIDE + s * 8) * 4));
            uint32_t bf0[4], bf1[4];
            LDSM(bf0, bbase + soff + (uint32_t)((0 * 16 * LDSTRIDE + s * 8) * 4));
            LDSM(bf1, bbase + soff + (uint32_t)((1 * 16 * LDSTRIDE + s * 8) * 4));
            MMA_J(0, bf0);
            LDSM(bf0, bbase + soff + (uint32_t)((2 * 16 * LDSTRIDE + s * 8) * 4));
            MMA_J(1, bf1);
            LDSM(bf1, bbase + soff + (uint32_t)((3 * 16 * LDSTRIDE + s * 8) * 4));
            MMA_J(2, bf0);
            MMA_J(3, bf1);
        }
    }
#undef PREFETCH
#undef LDSM
#undef MMA_PAIR
#undef MMA_J

    if (MODE == 1) {
        // GELU, round to tf32, store h [M x 1024]
        #pragma unroll
        for (int mt = 0; mt < 4; mt++) {
            const int r0 = bm + wm * 64 + mt * 16 + (lane >> 2);
            #pragma unroll
            for (int j = 0; j < 8; j++) {
                const int nc = bn + wn * 64 + j * 8 + (lane & 3) * 2;
                float* p0 = g_h + (size_t)r0 * CI + nc;
                float* p1 = p0 + (size_t)8 * CI;
                float2 v0, v1;
                v0.x = to_tf32(gelu_exact(acc[mt][j][0]));
                v0.y = to_tf32(gelu_exact(acc[mt][j][1]));
                v1.x = to_tf32(gelu_exact(acc[mt][j][2]));
                v1.y = to_tf32(gelu_exact(acc[mt][j][3]));
                *(float2*)p0 = v0;
                *(float2*)p1 = v1;
            }
        }
    } else {
        // residual + NCHW store (per-column 8-row runs -> full 32B sectors)
        #pragma unroll
        for (int mt = 0; mt < 4; mt++) {
            const int r0 = bm + wm * 64 + mt * 16 + (lane >> 2);
            const int r1 = r0 + 8;
            const int b0 = r0 / HW, hw0 = r0 - b0 * HW;
            const int b1 = r1 / HW, hw1 = r1 - b1 * HW;
            const size_t base0 = (size_t)b0 * C_TOT * HW + hw0;
            const size_t base1 = (size_t)b1 * C_TOT * HW + hw1;
            #pragma unroll
            for (int j = 0; j < 8; j++) {
                const int nc = bn + wn * 64 + j * 8 + (lane & 3) * 2;
                size_t i0 = base0 + (size_t)nc * HW;
                outp[i0]      = acc[mt][j][0] + xres[i0];
                outp[i0 + HW] = acc[mt][j][1] + xres[i0 + HW];
                size_t i1 = base1 + (size_t)nc * HW;
                outp[i1]      = acc[mt][j][2] + xres[i1];
                outp[i1 + HW] = acc[mt][j][3] + xres[i1 + HW];
            }
        }
    }
}

// ---------------- launch ----------------------------------------------------
extern "C" void kernel_launch(void* const* d_in, const int* in_sizes, int n_in,
                              void* d_out, int out_size) {
    const float* x   = (const float*)d_in[0];
    const float* wa1 = (const float*)d_in[1];
    const float* wb1 = (const float*)d_in[2];
    const float* wa2 = (const float*)d_in[3];
    const float* wb2 = (const float*)d_in[4];
    const float* bnw = (const float*)d_in[5];
    const float* bnb = (const float*)d_in[6];
    const float* bnm = (const float*)d_in[7];
    const float* bnv = (const float*)d_in[8];
    const float* fc1 = (const float*)d_in[9];
    const float* fc2 = (const float*)d_in[10];
    float* out = (float*)d_out;

    cudaFuncSetAttribute(gemm_tn_kernel<256, 1>,
                         cudaFuncAttributeMaxDynamicSharedMemorySize, GSMEM);
    cudaFuncSetAttribute(gemm_tn_kernel<1024, 2>,
                         cudaFuncAttributeMaxDynamicSharedMemorySize, GSMEM);

    convert_weights_kernel<<<(CI * C_TOT + 255) / 256, 256>>>(fc1, fc2);
    neocell_bn_kernel<<<dim3(14, 8, 32), 256>>>(x, wa1, wb1, wa2, wb2,
                                                bnw, bnb, bnm, bnv);
    gemm_tn_kernel<256, 1><<<dim3(8, 784), 128, GSMEM>>>(nullptr, nullptr);   // y @ fc1^T, GELU
    gemm_tn_kernel<1024, 2><<<dim3(2, 784), 128, GSMEM>>>(out, x);            // h @ fc2^T + x
}

// round 8
// speedup vs baseline: 1.5917x; 1.5917x over previous
#include <cuda_runtime.h>
#include <cuda_fp16.h>
#include <cstdint>

#define C_TOT 256
#define H_TOT 56
#define W_TOT 56
#define HW    3136
#define M_TOT 100352   // 32*56*56
#define CI    1024

// ---------------- scratch (static device globals; no allocations) ----------
__device__ __half g_y[(size_t)M_TOT * C_TOT];   // NHWC, BN'd, fp16
__device__ __half g_h[(size_t)M_TOT * CI];      // GELU output, fp16
__device__ __half g_w1[CI * C_TOT];             // fc1_w fp16
__device__ __half g_w2[C_TOT * CI];             // fc2_w fp16

__device__ __forceinline__ float gelu_exact(float v) {
    return 0.5f * v * (1.0f + erff(v * 0.70710678118654752440f));
}

// ---------------- kernel 1: round weights to fp16 --------------------------
__global__ void convert_weights_kernel(const float* __restrict__ fc1,
                                       const float* __restrict__ fc2) {
    int i = blockIdx.x * blockDim.x + threadIdx.x;
    if (i < CI * C_TOT) {
        g_w1[i] = __float2half_rn(fc1[i]);
        g_w2[i] = __float2half_rn(fc2[i]);
    }
}

// ---------------- kernel 2: NeoCell + BN -> y (NHWC, fp16) ------------------
__global__ __launch_bounds__(256)
void neocell_bn_kernel(const float* __restrict__ x,
                       const float* __restrict__ wa1, const float* __restrict__ wb1,
                       const float* __restrict__ wa2, const float* __restrict__ wb2,
                       const float* __restrict__ bnw, const float* __restrict__ bnb,
                       const float* __restrict__ bnm, const float* __restrict__ bnv) {
    __shared__ float tile[32 * 229];
    const int hs = blockIdx.x;
    const int c0 = blockIdx.y * 32;
    const int b  = blockIdx.z;
    const int h0 = hs * 4;

    const float* xb = x + ((size_t)b * C_TOT + c0) * HW + (size_t)h0 * W_TOT;
    for (int idx = threadIdx.x; idx < 32 * 4 * 56; idx += 256) {
        int c = idx / 224, r = idx % 224;
        int hh = r / 56, w = r % 56;
        tile[c * 229 + hh * 57 + w] = xb[(size_t)c * HW + hh * W_TOT + w];
    }
    __syncthreads();

    const int t  = threadIdx.x;
    const int c  = t & 31;
    const int s  = t >> 5;
    const int gc = c0 + c;
    const float scale = bnw[gc] * rsqrtf(bnv[gc] + 1e-5f);
    const float shift = bnb[gc] - bnm[gc] * scale;
    __half* ybase = g_y + ((size_t)b * H_TOT + h0) * W_TOT * C_TOT + gc;
    const float* tc = tile + c * 229;

    if (gc < 128) {
        const float a00 = wa1[gc*4+0], a01 = wa1[gc*4+1], a10 = wa1[gc*4+2], a11 = wa1[gc*4+3];
        const float b00 = wb1[gc*4+0], b01 = wb1[gc*4+1], b10 = wb1[gc*4+2], b11 = wb1[gc*4+3];
        for (int bi = s; bi < 56; bi += 8) {
            int n = bi / 28, m = bi % 28;
            const float* tp = tc + n * 2 * 57 + m * 2;
            float x00 = tp[0],  x01 = tp[1];
            float x10 = tp[57], x11 = tp[58];
            float t00 = a00 * x00 + a01 * x10;
            float t01 = a00 * x01 + a01 * x11;
            float t10 = a10 * x00 + a11 * x10;
            float t11 = a10 * x01 + a11 * x11;
            float y00 = t00 * b00 + t01 * b10;
            float y01 = t00 * b01 + t01 * b11;
            float y10 = t10 * b00 + t11 * b10;
            float y11 = t10 * b01 + t11 * b11;
            size_t base = ((size_t)(n * 2) * 56 + m * 2) * (size_t)C_TOT;
            ybase[base]            = __float2half_rn(y00 * scale + shift);
            ybase[base + 256]      = __float2half_rn(y01 * scale + shift);
            ybase[base + 56 * 256] = __float2half_rn(y10 * scale + shift);
            ybase[base + 57 * 256] = __float2half_rn(y11 * scale + shift);
        }
    } else {
        const float* wap = wa2 + (size_t)(gc - 128) * 16;
        const float* wbp = wb2 + (size_t)(gc - 128) * 16;
        float a[4][4], bw[4][4];
        #pragma unroll
        for (int i = 0; i < 4; i++)
            #pragma unroll
            for (int j = 0; j < 4; j++) { a[i][j] = wap[i*4+j]; bw[i][j] = wbp[i*4+j]; }
        for (int m = s; m < 14; m += 8) {
            float xv[4][4];
            #pragma unroll
            for (int i = 0; i < 4; i++)
                #pragma unroll
                for (int j = 0; j < 4; j++) xv[i][j] = tc[i * 57 + m * 4 + j];
            float tv[4][4];
            #pragma unroll
            for (int p = 0; p < 4; p++)
                #pragma unroll
                for (int j = 0; j < 4; j++)
                    tv[p][j] = a[p][0]*xv[0][j] + a[p][1]*xv[1][j]
                             + a[p][2]*xv[2][j] + a[p][3]*xv[3][j];
            #pragma unroll
            for (int p = 0; p < 4; p++)
                #pragma unroll
                for (int q = 0; q < 4; q++) {
                    float v = tv[p][0]*bw[0][q] + tv[p][1]*bw[1][q]
                            + tv[p][2]*bw[2][q] + tv[p][3]*bw[3][q];
                    ybase[((size_t)(p * 56) + m * 4 + q) * (size_t)C_TOT] =
                        __float2half_rn(v * scale + shift);
                }
        }
    }
}

// ---------------- GEMM (TN: C[m,n] = sum_k A[m,k]*B[n,k]), fp16 mma --------
// CTA tile 128x128, BK=32 halves, 8 warps (4m x 2n), warp tile 32x64, k16 steps.
// 4-stage cp.async ring, single __syncthreads per K-iteration, pipelined B frags.
#define BKH        32                   // halves per k-tile
#define LDH        40                   // halves per smem row (80 B, LDSM conflict-free)
#define STG_H      (128 * LDH)          // halves per matrix per stage
#define STG_B      (2 * STG_H * 2)      // bytes per stage (A + B) = 20480
#define NSTAGE     4
#define GSMEM      (NSTAGE * STG_B)     // 81920 bytes

template<int K, int MODE>
__global__ __launch_bounds__(256, 2)
void gemm_tn_kernel(float* __restrict__ outp, const float* __restrict__ xres) {
    extern __shared__ __align__(16) __half sm[];
    const __half* Amat = (MODE == 1) ? g_y : g_h;
    const __half* Bmat = (MODE == 1) ? g_w1 : g_w2;
    constexpr int KT = K / BKH;

    const int tid  = threadIdx.x;
    const int lane = tid & 31;
    const int warp = tid >> 5;
    const int wm   = warp & 3;          // 4 m-warps (32 rows each)
    const int wn   = warp >> 2;         // 2 n-warps (64 cols each)
    const int bm   = blockIdx.y * 128;
    const int bn   = blockIdx.x * 128;

    // global -> smem staging: 4 threads per row (32 halves = 4x16B), 64 rows/pass, 2 passes
    const int lrow = tid >> 2;          // 0..63
    const int lck  = tid & 3;           // 16B chunk (8 halves)
    const __half* Ap = Amat + (size_t)(bm + lrow) * K + lck * 8;
    const __half* Bp = Bmat + (size_t)(bn + lrow) * K + lck * 8;

    const uint32_t smb = (uint32_t)__cvta_generic_to_shared(sm);
    const uint32_t sa  = smb + (uint32_t)(lrow * LDH + lck * 8) * 2u;
    const uint32_t sb  = sa + (uint32_t)STG_H * 2u;

    float acc[2][8][4];
    #pragma unroll
    for (int i = 0; i < 2; i++)
        #pragma unroll
        for (int j = 0; j < 8; j++)
            #pragma unroll
            for (int q = 0; q < 4; q++) acc[i][j][q] = 0.f;

    // ldmatrix addressing: lane -> (row = lane%16, 16B half-column = lane/16)
    const int xrow  = lane & 15;
    const int xbyte = (lane >> 4) * 16;
    const uint32_t abase = smb + (uint32_t)((wm * 32 + xrow) * LDH * 2 + xbyte);
    const uint32_t bbase = smb + (uint32_t)(STG_H * 2 + (wn * 64 + xrow) * LDH * 2 + xbyte);

#define PREFETCH(ktv, stv) do {                                                          \
    const __half* ap_ = Ap + (ktv) * BKH;                                                \
    const __half* bp_ = Bp + (ktv) * BKH;                                                \
    uint32_t so_ = (uint32_t)((stv) * STG_B);                                            \
    _Pragma("unroll")                                                                    \
    for (int rp_ = 0; rp_ < 2; rp_++) {                                                  \
        asm volatile("cp.async.cg.shared.global [%0], [%1], 16;\n"                       \
                     :: "r"(sa + so_ + (uint32_t)(rp_ * 64 * LDH * 2)),                  \
                        "l"(ap_ + (size_t)(rp_ * 64) * K));                              \
        asm volatile("cp.async.cg.shared.global [%0], [%1], 16;\n"                       \
                     :: "r"(sb + so_ + (uint32_t)(rp_ * 64 * LDH * 2)),                  \
                        "l"(bp_ + (size_t)(rp_ * 64) * K));                              \
    }                                                                                    \
    asm volatile("cp.async.commit_group;\n");                                            \
} while (0)

#define LDSM(dst, addr)                                                                  \
    asm volatile("ldmatrix.sync.aligned.m8n8.x4.shared.b16 {%0,%1,%2,%3}, [%4];\n"       \
        : "=r"((dst)[0]), "=r"((dst)[1]), "=r"((dst)[2]), "=r"((dst)[3]) : "r"(addr))

#define MMA16(accj, afr, b0, b1)                                                         \
    asm volatile("mma.sync.aligned.m16n8k16.row.col.f32.f16.f16.f32 "                    \
        "{%0,%1,%2,%3}, {%4,%5,%6,%7}, {%8,%9}, {%0,%1,%2,%3};\n"                        \
        : "+f"((accj)[0]), "+f"((accj)[1]), "+f"((accj)[2]), "+f"((accj)[3])             \
        : "r"((afr)[0]), "r"((afr)[1]), "r"((afr)[2]), "r"((afr)[3]),                    \
          "r"(b0), "r"(b1))

// one ldmatrix.x4 on B covers two adjacent n8-tiles: tile(2j)={r0,r2}, tile(2j+1)={r1,r3}
#define MMA_J(jj, bfr) do {                                                              \
    MMA16(acc[0][2*(jj)],   af[0], (bfr)[0], (bfr)[2]);                                  \
    MMA16(acc[0][2*(jj)+1], af[0], (bfr)[1], (bfr)[3]);                                  \
    MMA16(acc[1][2*(jj)],   af[1], (bfr)[0], (bfr)[2]);                                  \
    MMA16(acc[1][2*(jj)+1], af[1], (bfr)[1], (bfr)[3]);                                  \
} while (0)

    // prologue: fill stages 0..2
    PREFETCH(0, 0);
    PREFETCH(1, 1);
    PREFETCH(2, 2);

    for (int kt = 0; kt < KT; ++kt) {
        const int st = kt & (NSTAGE - 1);
        if (kt + 2 < KT)      asm volatile("cp.async.wait_group 2;\n");
        else if (kt + 1 < KT) asm volatile("cp.async.wait_group 1;\n");
        else                  asm volatile("cp.async.wait_group 0;\n");
        __syncthreads();
        if (kt + 3 < KT) PREFETCH(kt + 3, (kt + 3) & (NSTAGE - 1));

        const uint32_t soff = (uint32_t)(st * STG_B);
        #pragma unroll
        for (int s = 0; s < 2; s++) {             // two k16 sub-steps per BK=32
            const uint32_t ko = soff + (uint32_t)(s * 32);   // 16 halves = 32 B
            uint32_t af[2][4];
            LDSM(af[0], abase + ko);
            LDSM(af[1], abase + ko + (uint32_t)(16 * LDH * 2));
            uint32_t bf0[4], bf1[4];
            LDSM(bf0, bbase + ko);
            LDSM(bf1, bbase + ko + (uint32_t)(16 * LDH * 2));
            MMA_J(0, bf0);
            LDSM(bf0, bbase + ko + (uint32_t)(32 * LDH * 2));
            MMA_J(1, bf1);
            LDSM(bf1, bbase + ko + (uint32_t)(48 * LDH * 2));
            MMA_J(2, bf0);
            MMA_J(3, bf1);
        }
    }
#undef PREFETCH
#undef LDSM
#undef MMA16
#undef MMA_J

    if (MODE == 1) {
        // GELU, round to fp16, store h [M x 1024]
        #pragma unroll
        for (int mt = 0; mt < 2; mt++) {
            const int r0 = bm + wm * 32 + mt * 16 + (lane >> 2);
            #pragma unroll
            for (int j = 0; j < 8; j++) {
                const int nc = bn + wn * 64 + j * 8 + (lane & 3) * 2;
                __half2* p0 = (__half2*)(g_h + (size_t)r0 * CI + nc);
                __half2* p1 = (__half2*)(g_h + (size_t)(r0 + 8) * CI + nc);
                *p0 = __floats2half2_rn(gelu_exact(acc[mt][j][0]), gelu_exact(acc[mt][j][1]));
                *p1 = __floats2half2_rn(gelu_exact(acc[mt][j][2]), gelu_exact(acc[mt][j][3]));
            }
        }
    } else {
        // residual + NCHW store (per-column 8-row runs -> full 32B sectors)
        #pragma unroll
        for (int mt = 0; mt < 2; mt++) {
            const int r0 = bm + wm * 32 + mt * 16 + (lane >> 2);
            const int r1 = r0 + 8;
            const int b0 = r0 / HW, hw0 = r0 - b0 * HW;
            const int b1 = r1 / HW, hw1 = r1 - b1 * HW;
            const size_t base0 = (size_t)b0 * C_TOT * HW + hw0;
            const size_t base1 = (size_t)b1 * C_TOT * HW + hw1;
            #pragma unroll
            for (int j = 0; j < 8; j++) {
                const int nc = bn + wn * 64 + j * 8 + (lane & 3) * 2;
                size_t i0 = base0 + (size_t)nc * HW;
                outp[i0]      = acc[mt][j][0] + xres[i0];
                outp[i0 + HW] = acc[mt][j][1] + xres[i0 + HW];
                size_t i1 = base1 + (size_t)nc * HW;
                outp[i1]      = acc[mt][j][2] + xres[i1];
                outp[i1 + HW] = acc[mt][j][3] + xres[i1 + HW];
            }
        }
    }
}

// ---------------- launch ----------------------------------------------------
extern "C" void kernel_launch(void* const* d_in, const int* in_sizes, int n_in,
                              void* d_out, int out_size) {
    const float* x   = (const float*)d_in[0];
    const float* wa1 = (const float*)d_in[1];
    const float* wb1 = (const float*)d_in[2];
    const float* wa2 = (const float*)d_in[3];
    const float* wb2 = (const float*)d_in[4];
    const float* bnw = (const float*)d_in[5];
    const float* bnb = (const float*)d_in[6];
    const float* bnm = (const float*)d_in[7];
    const float* bnv = (const float*)d_in[8];
    const float* fc1 = (const float*)d_in[9];
    const float* fc2 = (const float*)d_in[10];
    float* out = (float*)d_out;

    cudaFuncSetAttribute(gemm_tn_kernel<256, 1>,
                         cudaFuncAttributeMaxDynamicSharedMemorySize, GSMEM);
    cudaFuncSetAttribute(gemm_tn_kernel<1024, 2>,
                         cudaFuncAttributeMaxDynamicSharedMemorySize, GSMEM);

    convert_weights_kernel<<<(CI * C_TOT + 255) / 256, 256>>>(fc1, fc2);
    neocell_bn_kernel<<<dim3(14, 8, 32), 256>>>(x, wa1, wb1, wa2, wb2,
                                                bnw, bnb, bnm, bnv);
    gemm_tn_kernel<256, 1><<<dim3(8, 784), 256, GSMEM>>>(nullptr, nullptr);   // y @ fc1^T, GELU
    gemm_tn_kernel<1024, 2><<<dim3(2, 784), 256, GSMEM>>>(out, x);            // h @ fc2^T + x
}